// round 7
// baseline (speedup 1.0000x reference)
#include <cuda_runtime.h>
#include <cuda_fp16.h>
#include <cstdint>

#define NB    8
#define NPTS  4096
#define MSEL  1024
#define NC    64
#define KNBR  64
#define NCTR  (NB*MSEL)           // 8192
#define X_OUT_ELEMS (NCTR*256)
#define POS_OFF  X_OUT_ELEMS
#define BATCH_OFF (POS_OFF + NCTR*3)
#define SEED_OFF  (BATCH_OFF + NCTR)
#define TOTAL_OUT (SEED_OFF + NCTR)

// ---- global scratch (static: allocation-free rule) ----
__device__ int   g_idx[NCTR];
__device__ int   g_nbr[NCTR*KNBR];
__device__ int   g_cnt[NCTR];
__device__ float qb_g[(size_t)NB*NPTS*128];

// ============================================================
// 1) Fused FPS (blocks 0..7) + per-point layer-1 qb (blocks 8+)
// ============================================================
#define QPB2 64
#define FPS_SMEM (3*NPTS*4 + 512)
__global__ __launch_bounds__(512) void fps_qb_kernel(
    const float* __restrict__ pos, const float* __restrict__ x,
    const float* __restrict__ W1, const float* __restrict__ b1)
{
    extern __shared__ float fsm[];
    int t = threadIdx.x;

    if (blockIdx.x < NB) {
        // ---------------- FPS ----------------
        float* sx = fsm;
        float* sy = fsm + NPTS;
        float* sz = fsm + 2*NPTS;
        unsigned long long* warpbest = (unsigned long long*)(fsm + 3*NPTS);  // [2][16]
        int g = blockIdx.x;
        const float* p = pos + (size_t)g * NPTS * 3;
        int lane = t & 31, wid = t >> 5;

        for (int i = t; i < NPTS; i += 512) {
            sx[i] = p[3*i]; sy[i] = p[3*i+1]; sz[i] = p[3*i+2];
        }
        __syncthreads();

        const int i0 = t * 8;
        float px[8], py[8], pz[8], mn[8];
        #pragma unroll
        for (int j = 0; j < 8; j++) {
            px[j] = sx[i0+j]; py[j] = sy[i0+j]; pz[j] = sz[i0+j]; mn[j] = 1e10f;
        }
        float lx = sx[0], ly = sy[0], lz = sz[0];
        if (t == 0) g_idx[g*MSEL] = g*NPTS;

        for (int it = 1; it < MSEL; it++) {
            float bv = -1.0f; int bi = i0;
            #pragma unroll
            for (int j = 0; j < 8; j++) {
                float dx = __fsub_rn(px[j], lx), dy = __fsub_rn(py[j], ly), dz = __fsub_rn(pz[j], lz);
                float d  = __fadd_rn(__fadd_rn(__fmul_rn(dx,dx), __fmul_rn(dy,dy)), __fmul_rn(dz,dz));
                mn[j] = fminf(mn[j], d);
                if (mn[j] > bv) { bv = mn[j]; bi = i0 + j; }
            }
            unsigned long long key =
                ((unsigned long long)__float_as_uint(bv) << 32) | (unsigned)(NPTS - 1 - bi);
            #pragma unroll
            for (int o = 16; o > 0; o >>= 1) {
                unsigned long long ok = __shfl_xor_sync(0xffffffffu, key, o);
                if (ok > key) key = ok;
            }
            if (lane == 0) warpbest[(it & 1)*16 + wid] = key;
            __syncthreads();
            unsigned long long k2 = warpbest[(it & 1)*16 + (lane & 15)];
            #pragma unroll
            for (int o = 8; o > 0; o >>= 1) {
                unsigned long long ok = __shfl_xor_sync(0xffffffffu, k2, o);
                if (ok > k2) k2 = ok;
            }
            int nxt = NPTS - 1 - (int)(k2 & 0xffffffffu);
            lx = sx[nxt]; ly = sy[nxt]; lz = sz[nxt];
            if (t == 0) g_idx[g*MSEL + it] = g*NPTS + nxt;
        }
    } else {
        // ---------------- qb: 64 points per block ----------------
        float* sxq = fsm;                 // 64*68
        float* spq = fsm + QPB2*68;       // 64*3
        int base = (blockIdx.x - NB) * QPB2;
        for (int idx = t; idx < QPB2*64; idx += 512) {
            int pp = idx >> 6, k = idx & 63;
            sxq[pp*68 + k] = x[(size_t)(base + pp)*64 + k];
        }
        if (t < QPB2*3) spq[t] = pos[(size_t)base*3 + t];
        __syncthreads();
        int col = t & 127, sg = t >> 7;   // 4 subgroups x 16 points
        float acc[16];
        float bb = b1[col];
        #pragma unroll
        for (int q = 0; q < 16; q++) acc[q] = bb;
        for (int k = 0; k < 64; k++) {
            float w = W1[k*128 + col];
            #pragma unroll
            for (int q = 0; q < 16; q++)
                acc[q] = fmaf(sxq[(sg*16 + q)*68 + k], w, acc[q]);
        }
        float wx = W1[64*128 + col], wy = W1[65*128 + col], wz = W1[66*128 + col];
        #pragma unroll
        for (int q = 0; q < 16; q++) {
            int pp = sg*16 + q;
            acc[q] = fmaf(spq[pp*3+0], wx, acc[q]);
            acc[q] = fmaf(spq[pp*3+1], wy, acc[q]);
            acc[q] = fmaf(spq[pp*3+2], wz, acc[q]);
            qb_g[(size_t)(base + pp)*128 + col] = acc[q];
        }
    }
}

// ============================================================
// 2) Radius + top-64, smem-cached points, 16 centroids/block
// ============================================================
#define CAP 1024
#define NBR_CPB 16
#define NBR_SMEM (3*NPTS*4 + CAP*8)    // 49152 + 8192 = 57344
__global__ __launch_bounds__(256) void nbr_kernel(const float* __restrict__ pos) {
    extern __shared__ char nsm[];
    float* sx = (float*)nsm;
    float* sy = sx + NPTS;
    float* sz = sy + NPTS;
    unsigned long long* keys = (unsigned long long*)(nsm + 3*NPTS*4);
    __shared__ int s_cnt, s_osel;

    int t = threadIdx.x;
    int g  = blockIdx.x >> 6;                    // 64 blocks per graph
    int cb = (blockIdx.x & 63) * NBR_CPB;        // centroid offset in graph
    const float* p = pos + (size_t)g * NPTS * 3;
    for (int i = t; i < NPTS; i += 256) {
        sx[i] = p[3*i]; sy[i] = p[3*i+1]; sz[i] = p[3*i+2];
    }
    __syncthreads();
    const float RR = 0.04f;

    for (int cc = 0; cc < NBR_CPB; cc++) {
        int c = g*MSEL + cb + cc;
        int li = g_idx[c] - g*NPTS;
        float cx = sx[li], cy = sy[li], cz = sz[li];
        if (t == 0) { s_cnt = 0; s_osel = 0; }
        __syncthreads();
        for (int i = t; i < NPTS; i += 256) {
            float dx = __fsub_rn(cx, sx[i]);
            float dy = __fsub_rn(cy, sy[i]);
            float dz = __fsub_rn(cz, sz[i]);
            float d2 = __fadd_rn(__fadd_rn(__fmul_rn(dx,dx), __fmul_rn(dy,dy)), __fmul_rn(dz,dz));
            if (d2 < RR) {
                int slot = atomicAdd(&s_cnt, 1);
                if (slot < CAP)
                    keys[slot] = ((unsigned long long)__float_as_uint(d2) << 32) | (unsigned)i;
            }
        }
        __syncthreads();
        int cnt = min(s_cnt, CAP);
        if (cnt <= KNBR) {
            for (int j = t; j < cnt; j += 256)
                g_nbr[c*KNBR + j] = (int)(keys[j] & 0xffffffffu);
            if (t == 0) g_cnt[c] = cnt;
        } else {
            for (int j = t; j < cnt; j += 256) {
                unsigned long long kj = keys[j];
                int rank = 0;
                for (int q = 0; q < cnt; q++) rank += (keys[q] < kj);
                if (rank < KNBR) {
                    int o = atomicAdd(&s_osel, 1);
                    g_nbr[c*KNBR + o] = (int)(kj & 0xffffffffu);
                }
            }
            if (t == 0) g_cnt[c] = KNBR;
        }
        __syncthreads();
    }
}

// ============================================================
// 3) Persistent fused edge MLP: 256 thr, 4 centroids/tile, LDSM
// ============================================================
#define STR    272
#define O_W2T  0u
#define O_W3T  34816u
#define O_AH   104448u
#define O_B2   174080u
#define O_B3   174592u
#define O_PART 175616u
#define O_S    183808u
#define O_META 185856u
#define O_CTR  185872u
#define SMEM_EDGE 185984

__device__ __forceinline__ void mma16816(float* d, const uint32_t* a,
                                         uint32_t b0, uint32_t b1) {
    asm volatile("mma.sync.aligned.m16n8k16.row.col.f32.f16.f16.f32 "
        "{%0,%1,%2,%3}, {%4,%5,%6,%7}, {%8,%9}, {%0,%1,%2,%3};"
        : "+f"(d[0]), "+f"(d[1]), "+f"(d[2]), "+f"(d[3])
        : "r"(a[0]), "r"(a[1]), "r"(a[2]), "r"(a[3]), "r"(b0), "r"(b1));
}
__device__ __forceinline__ void ldsm4(uint32_t* r, uint32_t addr) {
    asm volatile("ldmatrix.sync.aligned.m8n8.x4.shared.b16 {%0,%1,%2,%3}, [%4];"
        : "=r"(r[0]), "=r"(r[1]), "=r"(r[2]), "=r"(r[3]) : "r"(addr));
}
__device__ __forceinline__ uint32_t packh2(float a, float b) {
    __half2 h = __floats2half2_rn(a, b);
    return *(uint32_t*)&h;
}
__device__ __forceinline__ uint32_t smem_u32(const void* p) {
    uint32_t a;
    asm("{ .reg .u64 t; cvta.to.shared.u64 t, %1; cvt.u32.u64 %0, t; }" : "=r"(a) : "l"(p));
    return a;
}

__global__ __launch_bounds__(256, 1) void edge_kernel(
    const float* __restrict__ pos, const float* __restrict__ W1,
    const float* __restrict__ W2, const float* __restrict__ b2,
    const float* __restrict__ W3, const float* __restrict__ b3,
    float* __restrict__ out)
{
    extern __shared__ char sm[];
    float* b2s  = (float*)(sm + O_B2);
    float* b3s  = (float*)(sm + O_B3);
    float* part = (float*)(sm + O_PART);
    float* s_sm = (float*)(sm + O_S);
    int*   meta = (int*)(sm + O_META);
    float* ctr  = (float*)(sm + O_CTR);

    int t = threadIdx.x, wid = t >> 5, lane = t & 31;
    int g4 = lane >> 2, tig = lane & 3;
    int m0 = wid * 32;
    int colid = t & 127;

    // ldmatrix per-lane base addresses
    uint32_t smb  = smem_u32(sm);
    uint32_t aA   = smb + O_AH + (uint32_t)(m0 + (lane & 15))*STR + ((lane >> 4)*16);
    uint32_t rowB = ((lane >> 4) << 3) | (lane & 7);
    uint32_t colB = ((lane >> 3) & 1) * 16;
    uint32_t bB2  = smb + O_W2T + rowB*STR + colB;
    uint32_t bB3  = smb + O_W3T + rowB*STR + colB;

    // one-time: weights -> fp16 padded smem (transposed [n][k])
    for (int idx = t; idx < 128*128; idx += 256) {
        int k = idx >> 7, n = idx & 127;
        *(__half*)(sm + O_W2T + (uint32_t)n*STR + k*2) = __float2half_rn(W2[idx]);
    }
    for (int idx = t; idx < 128*256; idx += 256) {
        int k = idx >> 8, n = idx & 255;
        *(__half*)(sm + O_W3T + (uint32_t)n*STR + k*2) = __float2half_rn(W3[idx]);
    }
    if (t < 128) { b2s[t] = b2[t]; b3s[t] = b3[t]; b3s[128 + t] = b3[128 + t]; }
    float w1x = W1[64*128 + colid], w1y = W1[65*128 + colid], w1z = W1[66*128 + colid];
    __syncthreads();

    for (int tile = blockIdx.x; tile < NCTR/4; tile += 148) {
        int c0 = 4 * tile;
        int g  = c0 >> 10;
        if (t < 4) {
            meta[t] = g_cnt[c0 + t];
            int ci = g_idx[c0 + t];
            ctr[t*3+0] = pos[3*ci]; ctr[t*3+1] = pos[3*ci+1]; ctr[t*3+2] = pos[3*ci+2];
        }
        __syncthreads();
        {
            int cl0 = t >> 7;
            s_sm[t]       = ctr[cl0*3+0]*w1x + ctr[cl0*3+1]*w1y + ctr[cl0*3+2]*w1z;
            s_sm[t + 256] = ctr[(cl0+2)*3+0]*w1x + ctr[(cl0+2)*3+1]*w1y + ctr[(cl0+2)*3+2]*w1z;
        }
        __syncthreads();

        // A1 build: row r = t
        {
            int r = t, cl = r >> 6;
            bool valid = (r & 63) < meta[cl];
            int jg = valid ? (g*NPTS + g_nbr[(c0 + cl)*KNBR + (r & 63)]) : 0;
            const float4* qrow = (const float4*)(qb_g + (size_t)jg * 128);
            const float4* sv   = (const float4*)(s_sm + cl*128);
            char* arow = sm + O_AH + (uint32_t)r*STR;
            #pragma unroll
            for (int i = 0; i < 32; i++) {
                uint32_t u0 = 0, u1 = 0;
                if (valid) {
                    float4 q = qrow[i], s4 = sv[i];
                    u0 = packh2(fmaxf(q.x - s4.x, 0.f), fmaxf(q.y - s4.y, 0.f));
                    u1 = packh2(fmaxf(q.z - s4.z, 0.f), fmaxf(q.w - s4.w, 0.f));
                }
                *(uint32_t*)(arow + i*8)     = u0;
                *(uint32_t*)(arow + i*8 + 4) = u1;
            }
        }
        __syncwarp();

        // layer 2: h2 = relu(A1 @ W2 + b2); H2 overwrites A1 (own rows)
        {
            float acc[2][16][4];
            #pragma unroll
            for (int mt = 0; mt < 2; mt++)
                #pragma unroll
                for (int n = 0; n < 16; n++)
                    #pragma unroll
                    for (int q = 0; q < 4; q++) acc[mt][n][q] = 0.f;
            #pragma unroll
            for (int k = 0; k < 8; k++) {
                uint32_t a0[4], a1[4];
                ldsm4(a0, aA + k*32);
                ldsm4(a1, aA + 16*STR + k*32);
                #pragma unroll
                for (int n2 = 0; n2 < 8; n2++) {
                    uint32_t b[4];
                    ldsm4(b, bB2 + n2*(16*STR) + k*32);
                    mma16816(acc[0][2*n2],   a0, b[0], b[1]);
                    mma16816(acc[1][2*n2],   a1, b[0], b[1]);
                    mma16816(acc[0][2*n2+1], a0, b[2], b[3]);
                    mma16816(acc[1][2*n2+1], a1, b[2], b[3]);
                }
            }
            #pragma unroll
            for (int mt = 0; mt < 2; mt++) {
                int r0 = m0 + mt*16 + g4;
                #pragma unroll
                for (int n = 0; n < 16; n++) {
                    int col = n*8 + tig*2;
                    *(uint32_t*)(sm + O_AH + (uint32_t)r0*STR + col*2) =
                        packh2(fmaxf(acc[mt][n][0] + b2s[col], 0.f),
                               fmaxf(acc[mt][n][1] + b2s[col+1], 0.f));
                    *(uint32_t*)(sm + O_AH + (uint32_t)(r0+8)*STR + col*2) =
                        packh2(fmaxf(acc[mt][n][2] + b2s[col], 0.f),
                               fmaxf(acc[mt][n][3] + b2s[col+1], 0.f));
                }
            }
        }
        __syncwarp();

        // layer 3: relu(h2 @ W3 + b3), mask, column-max
        {
            int ncnt = meta[wid >> 1];
            int rb0  = (wid & 1) * 32;
            #pragma unroll
            for (int nh = 0; nh < 2; nh++) {
                float acc[2][16][4];
                #pragma unroll
                for (int mt = 0; mt < 2; mt++)
                    #pragma unroll
                    for (int n = 0; n < 16; n++)
                        #pragma unroll
                        for (int q = 0; q < 4; q++) acc[mt][n][q] = 0.f;
                #pragma unroll
                for (int k = 0; k < 8; k++) {
                    uint32_t a0[4], a1[4];
                    ldsm4(a0, aA + k*32);
                    ldsm4(a1, aA + 16*STR + k*32);
                    #pragma unroll
                    for (int n2 = 0; n2 < 8; n2++) {
                        uint32_t b[4];
                        ldsm4(b, bB3 + (nh*128 + n2*16)*STR + k*32);
                        mma16816(acc[0][2*n2],   a0, b[0], b[1]);
                        mma16816(acc[1][2*n2],   a1, b[0], b[1]);
                        mma16816(acc[0][2*n2+1], a0, b[2], b[3]);
                        mma16816(acc[1][2*n2+1], a1, b[2], b[3]);
                    }
                }
                #pragma unroll
                for (int n = 0; n < 16; n++) {
                    int col = nh*128 + n*8 + tig*2;
                    float bv0 = b3s[col], bv1 = b3s[col+1];
                    float mx0 = -1e30f, mx1 = -1e30f;
                    #pragma unroll
                    for (int mt = 0; mt < 2; mt++) {
                        int rlo = rb0 + mt*16 + g4;
                        bool vlo = rlo < ncnt, vhi = (rlo + 8) < ncnt;
                        if (vlo) {
                            mx0 = fmaxf(mx0, fmaxf(acc[mt][n][0] + bv0, 0.f));
                            mx1 = fmaxf(mx1, fmaxf(acc[mt][n][1] + bv1, 0.f));
                        }
                        if (vhi) {
                            mx0 = fmaxf(mx0, fmaxf(acc[mt][n][2] + bv0, 0.f));
                            mx1 = fmaxf(mx1, fmaxf(acc[mt][n][3] + bv1, 0.f));
                        }
                    }
                    #pragma unroll
                    for (int o = 4; o <= 16; o <<= 1) {
                        mx0 = fmaxf(mx0, __shfl_xor_sync(0xffffffffu, mx0, o));
                        mx1 = fmaxf(mx1, __shfl_xor_sync(0xffffffffu, mx1, o));
                    }
                    if (g4 == 0) {
                        part[wid*256 + col]     = mx0;
                        part[wid*256 + col + 1] = mx1;
                    }
                }
            }
        }
        __syncthreads();

        {
            int col = t;
            #pragma unroll
            for (int cl = 0; cl < 4; cl++) {
                float v = fmaxf(part[(2*cl)*256 + (col & 255)], part[(2*cl + 1)*256 + (col & 255)]);
                if (col < 256)
                    out[(size_t)(c0 + cl)*256 + col] = (meta[cl] > 0) ? v : 0.f;
            }
        }
        __syncthreads();
    }
}

// ============================================================
// 4) Tail outputs
// ============================================================
__global__ void tail_kernel(const float* __restrict__ pos, float* __restrict__ out,
                            int write_tail) {
    int i = blockIdx.x * blockDim.x + threadIdx.x;
    if (i >= NCTR || !write_tail) return;
    int fi = g_idx[i];
    out[POS_OFF + 3*i + 0] = pos[3*fi + 0];
    out[POS_OFF + 3*i + 1] = pos[3*fi + 1];
    out[POS_OFF + 3*i + 2] = pos[3*fi + 2];
    out[BATCH_OFF + i] = (float)(fi >> 12);
    out[SEED_OFF  + i] = (float)fi;
}

// ============================================================
extern "C" void kernel_launch(void* const* d_in, const int* in_sizes, int n_in,
                              void* d_out, int out_size) {
    const float* x   = (const float*)d_in[0];
    const float* pos = (const float*)d_in[1];
    const float* W1  = (const float*)d_in[4];
    const float* b1  = (const float*)d_in[5];
    const float* W2  = (const float*)d_in[6];
    const float* b2  = (const float*)d_in[7];
    const float* W3  = (const float*)d_in[8];
    const float* b3  = (const float*)d_in[9];
    float* out = (float*)d_out;

    cudaFuncSetAttribute(fps_qb_kernel, cudaFuncAttributeMaxDynamicSharedMemorySize, FPS_SMEM);
    cudaFuncSetAttribute(nbr_kernel, cudaFuncAttributeMaxDynamicSharedMemorySize, NBR_SMEM);
    cudaFuncSetAttribute(edge_kernel, cudaFuncAttributeMaxDynamicSharedMemorySize, SMEM_EDGE);

    fps_qb_kernel<<<NB + NB*NPTS/QPB2, 512, FPS_SMEM>>>(pos, x, W1, b1);
    nbr_kernel<<<NB*64, 256, NBR_SMEM>>>(pos);
    edge_kernel<<<148, 256, SMEM_EDGE>>>(pos, W1, W2, b2, W3, b3, out);
    tail_kernel<<<(NCTR + 255)/256, 256>>>(pos, out, out_size >= TOTAL_OUT ? 1 : 0);
}

// round 8
// speedup vs baseline: 1.0979x; 1.0979x over previous
#include <cuda_runtime.h>
#include <cuda_fp16.h>
#include <cstdint>

#define NB    8
#define NPTS  4096
#define MSEL  1024
#define NC    64
#define KNBR  64
#define NCTR  (NB*MSEL)           // 8192
#define X_OUT_ELEMS (NCTR*256)
#define POS_OFF  X_OUT_ELEMS
#define BATCH_OFF (POS_OFF + NCTR*3)
#define SEED_OFF  (BATCH_OFF + NCTR)
#define TOTAL_OUT (SEED_OFF + NCTR)

// ---- global scratch (static: allocation-free rule) ----
__device__ int   g_idx[NCTR];
__device__ int   g_nbr[NCTR*KNBR];
__device__ int   g_cnt[NCTR];
__device__ float qb_g[(size_t)NB*NPTS*128];

// ============================================================
// 1) FPS: 512 threads x 8 pts, smem pos cache, 1 barrier/iter
//    (exact R6 version — 871us baseline component)
// ============================================================
#define FPS_SMEM (3*NPTS*4 + 512)
__global__ __launch_bounds__(512) void fps_kernel(const float* __restrict__ pos) {
    extern __shared__ float fsm[];
    float* sx = fsm;
    float* sy = fsm + NPTS;
    float* sz = fsm + 2*NPTS;
    unsigned long long* warpbest = (unsigned long long*)(fsm + 3*NPTS);  // [2][16]

    int g = blockIdx.x;
    const float* p = pos + (size_t)g * NPTS * 3;
    int t = threadIdx.x, lane = t & 31, wid = t >> 5;

    for (int i = t; i < NPTS; i += 512) {
        sx[i] = p[3*i]; sy[i] = p[3*i+1]; sz[i] = p[3*i+2];
    }
    __syncthreads();

    const int i0 = t * 8;
    float px[8], py[8], pz[8], mn[8];
    #pragma unroll
    for (int j = 0; j < 8; j++) {
        px[j] = sx[i0+j]; py[j] = sy[i0+j]; pz[j] = sz[i0+j]; mn[j] = 1e10f;
    }
    float lx = sx[0], ly = sy[0], lz = sz[0];
    if (t == 0) g_idx[g*MSEL] = g*NPTS;

    for (int it = 1; it < MSEL; it++) {
        float bv = -1.0f; int bi = i0;
        #pragma unroll
        for (int j = 0; j < 8; j++) {
            float dx = __fsub_rn(px[j], lx), dy = __fsub_rn(py[j], ly), dz = __fsub_rn(pz[j], lz);
            float d  = __fadd_rn(__fadd_rn(__fmul_rn(dx,dx), __fmul_rn(dy,dy)), __fmul_rn(dz,dz));
            mn[j] = fminf(mn[j], d);
            if (mn[j] > bv) { bv = mn[j]; bi = i0 + j; }
        }
        unsigned long long key =
            ((unsigned long long)__float_as_uint(bv) << 32) | (unsigned)(NPTS - 1 - bi);
        #pragma unroll
        for (int o = 16; o > 0; o >>= 1) {
            unsigned long long ok = __shfl_xor_sync(0xffffffffu, key, o);
            if (ok > key) key = ok;
        }
        if (lane == 0) warpbest[(it & 1)*16 + wid] = key;
        __syncthreads();
        unsigned long long k2 = warpbest[(it & 1)*16 + (lane & 15)];
        #pragma unroll
        for (int o = 8; o > 0; o >>= 1) {
            unsigned long long ok = __shfl_xor_sync(0xffffffffu, k2, o);
            if (ok > k2) k2 = ok;
        }
        int nxt = NPTS - 1 - (int)(k2 & 0xffffffffu);
        lx = sx[nxt]; ly = sy[nxt]; lz = sz[nxt];
        if (t == 0) g_idx[g*MSEL + it] = g*NPTS + nxt;
    }
}

// ============================================================
// 2) Radius + top-64 (exact R6 streaming version)
// ============================================================
#define CAP 1024
__global__ __launch_bounds__(256) void nbr_kernel(const float* __restrict__ pos) {
    __shared__ unsigned long long keys[CAP];
    __shared__ int s_cnt, s_osel;
    __shared__ float s_c[3];
    int c = blockIdx.x;
    int g = c >> 10;
    int t = threadIdx.x;
    if (t == 0) {
        int ci = g_idx[c];
        s_c[0] = pos[3*ci]; s_c[1] = pos[3*ci+1]; s_c[2] = pos[3*ci+2];
        s_cnt = 0; s_osel = 0;
    }
    __syncthreads();
    float cx = s_c[0], cy = s_c[1], cz = s_c[2];
    const float* p = pos + (size_t)g * NPTS * 3;
    const float RR = 0.04f;
    for (int i = t; i < NPTS; i += 256) {
        float dx = __fsub_rn(cx, p[3*i]);
        float dy = __fsub_rn(cy, p[3*i+1]);
        float dz = __fsub_rn(cz, p[3*i+2]);
        float d2 = __fadd_rn(__fadd_rn(__fmul_rn(dx,dx), __fmul_rn(dy,dy)), __fmul_rn(dz,dz));
        if (d2 < RR) {
            int slot = atomicAdd(&s_cnt, 1);
            if (slot < CAP)
                keys[slot] = ((unsigned long long)__float_as_uint(d2) << 32) | (unsigned)i;
        }
    }
    __syncthreads();
    int cnt = min(s_cnt, CAP);
    if (cnt <= KNBR) {
        for (int j = t; j < cnt; j += 256)
            g_nbr[c*KNBR + j] = (int)(keys[j] & 0xffffffffu);
        if (t == 0) g_cnt[c] = cnt;
    } else {
        for (int j = t; j < cnt; j += 256) {
            unsigned long long kj = keys[j];
            int rank = 0;
            for (int q = 0; q < cnt; q++) rank += (keys[q] < kj);
            if (rank < KNBR) {
                int o = atomicAdd(&s_osel, 1);
                g_nbr[c*KNBR + o] = (int)(kj & 0xffffffffu);
            }
        }
        if (t == 0) g_cnt[c] = KNBR;
    }
}

// ============================================================
// 3a) Per-point layer-1, 16 points/block (exact R6 version)
// ============================================================
#define QPB 16
__global__ __launch_bounds__(128) void qb_kernel(
    const float* __restrict__ x, const float* __restrict__ pos,
    const float* __restrict__ W1, const float* __restrict__ b1)
{
    __shared__ float sx[QPB*68];
    __shared__ float sp[QPB*3];
    int base = blockIdx.x * QPB;
    int t = threadIdx.x;
    for (int idx = t; idx < QPB*64; idx += 128) {
        int pp = idx >> 6, k = idx & 63;
        sx[pp*68 + k] = x[(size_t)(base + pp)*64 + k];
    }
    if (t < QPB*3) sp[t] = pos[(size_t)base*3 + t];
    __syncthreads();
    float acc[QPB];
    float bb = b1[t];
    #pragma unroll
    for (int q = 0; q < QPB; q++) acc[q] = bb;
    for (int k = 0; k < 64; k++) {
        float w = W1[k*128 + t];
        #pragma unroll
        for (int q = 0; q < QPB; q++) acc[q] = fmaf(sx[q*68 + k], w, acc[q]);
    }
    float wx = W1[64*128 + t], wy = W1[65*128 + t], wz = W1[66*128 + t];
    #pragma unroll
    for (int q = 0; q < QPB; q++) {
        acc[q] = fmaf(sp[q*3+0], wx, acc[q]);
        acc[q] = fmaf(sp[q*3+1], wy, acc[q]);
        acc[q] = fmaf(sp[q*3+2], wz, acc[q]);
        qb_g[(size_t)(base + q)*128 + t] = acc[q];
    }
}

// ============================================================
// 3b) Persistent fused edge MLP: 256 thr, 4 centroids/tile,
//     LDSM fragment loads (the ONE change vs the R6 871us code)
// ============================================================
#define STR    272
#define O_W2T  0u
#define O_W3T  34816u
#define O_AH   104448u
#define O_B2   174080u
#define O_B3   174592u
#define O_PART 175616u
#define O_S    183808u
#define O_META 185856u
#define O_CTR  185872u
#define SMEM_EDGE 185984

__device__ __forceinline__ void mma16816(float* d, const uint32_t* a,
                                         uint32_t b0, uint32_t b1) {
    asm volatile("mma.sync.aligned.m16n8k16.row.col.f32.f16.f16.f32 "
        "{%0,%1,%2,%3}, {%4,%5,%6,%7}, {%8,%9}, {%0,%1,%2,%3};"
        : "+f"(d[0]), "+f"(d[1]), "+f"(d[2]), "+f"(d[3])
        : "r"(a[0]), "r"(a[1]), "r"(a[2]), "r"(a[3]), "r"(b0), "r"(b1));
}
__device__ __forceinline__ void ldsm4(uint32_t* r, uint32_t addr) {
    asm volatile("ldmatrix.sync.aligned.m8n8.x4.shared.b16 {%0,%1,%2,%3}, [%4];"
        : "=r"(r[0]), "=r"(r[1]), "=r"(r[2]), "=r"(r[3]) : "r"(addr));
}
__device__ __forceinline__ uint32_t packh2(float a, float b) {
    __half2 h = __floats2half2_rn(a, b);
    return *(uint32_t*)&h;
}
__device__ __forceinline__ uint32_t smem_u32(const void* p) {
    uint32_t a;
    asm("{ .reg .u64 t; cvta.to.shared.u64 t, %1; cvt.u32.u64 %0, t; }" : "=r"(a) : "l"(p));
    return a;
}

__global__ __launch_bounds__(256, 1) void edge_kernel(
    const float* __restrict__ pos, const float* __restrict__ W1,
    const float* __restrict__ W2, const float* __restrict__ b2,
    const float* __restrict__ W3, const float* __restrict__ b3,
    float* __restrict__ out)
{
    extern __shared__ char sm[];
    float* b2s  = (float*)(sm + O_B2);
    float* b3s  = (float*)(sm + O_B3);
    float* part = (float*)(sm + O_PART);
    float* s_sm = (float*)(sm + O_S);
    int*   meta = (int*)(sm + O_META);
    float* ctr  = (float*)(sm + O_CTR);

    int t = threadIdx.x, wid = t >> 5, lane = t & 31;
    int g4 = lane >> 2, tig = lane & 3;
    int m0 = wid * 32;
    int colid = t & 127;

    // ldmatrix per-lane base addresses
    uint32_t smb  = smem_u32(sm);
    uint32_t aA   = smb + O_AH + (uint32_t)(m0 + (lane & 15))*STR + ((lane >> 4)*16);
    uint32_t rowB = ((lane >> 4) << 3) | (lane & 7);
    uint32_t colB = ((lane >> 3) & 1) * 16;
    uint32_t bB2  = smb + O_W2T + rowB*STR + colB;
    uint32_t bB3  = smb + O_W3T + rowB*STR + colB;

    // one-time: weights -> fp16 padded smem (transposed [n][k])
    for (int idx = t; idx < 128*128; idx += 256) {
        int k = idx >> 7, n = idx & 127;
        *(__half*)(sm + O_W2T + (uint32_t)n*STR + k*2) = __float2half_rn(W2[idx]);
    }
    for (int idx = t; idx < 128*256; idx += 256) {
        int k = idx >> 8, n = idx & 255;
        *(__half*)(sm + O_W3T + (uint32_t)n*STR + k*2) = __float2half_rn(W3[idx]);
    }
    if (t < 128) { b2s[t] = b2[t]; b3s[t] = b3[t]; b3s[128 + t] = b3[128 + t]; }
    float w1x = W1[64*128 + colid], w1y = W1[65*128 + colid], w1z = W1[66*128 + colid];
    __syncthreads();

    for (int tile = blockIdx.x; tile < NCTR/4; tile += 148) {
        int c0 = 4 * tile;
        int g  = c0 >> 10;
        if (t < 4) {
            meta[t] = g_cnt[c0 + t];
            int ci = g_idx[c0 + t];
            ctr[t*3+0] = pos[3*ci]; ctr[t*3+1] = pos[3*ci+1]; ctr[t*3+2] = pos[3*ci+2];
        }
        __syncthreads();
        {
            int cl0 = t >> 7;
            s_sm[t]       = ctr[cl0*3+0]*w1x + ctr[cl0*3+1]*w1y + ctr[cl0*3+2]*w1z;
            s_sm[t + 256] = ctr[(cl0+2)*3+0]*w1x + ctr[(cl0+2)*3+1]*w1y + ctr[(cl0+2)*3+2]*w1z;
        }
        __syncthreads();

        // A1 build: row r = t
        {
            int r = t, cl = r >> 6;
            bool valid = (r & 63) < meta[cl];
            int jg = valid ? (g*NPTS + g_nbr[(c0 + cl)*KNBR + (r & 63)]) : 0;
            const float4* qrow = (const float4*)(qb_g + (size_t)jg * 128);
            const float4* sv   = (const float4*)(s_sm + cl*128);
            char* arow = sm + O_AH + (uint32_t)r*STR;
            #pragma unroll
            for (int i = 0; i < 32; i++) {
                uint32_t u0 = 0, u1 = 0;
                if (valid) {
                    float4 q = qrow[i], s4 = sv[i];
                    u0 = packh2(fmaxf(q.x - s4.x, 0.f), fmaxf(q.y - s4.y, 0.f));
                    u1 = packh2(fmaxf(q.z - s4.z, 0.f), fmaxf(q.w - s4.w, 0.f));
                }
                *(uint32_t*)(arow + i*8)     = u0;
                *(uint32_t*)(arow + i*8 + 4) = u1;
            }
        }
        __syncwarp();

        // layer 2: h2 = relu(A1 @ W2 + b2); H2 overwrites A1 (own rows)
        {
            float acc[2][16][4];
            #pragma unroll
            for (int mt = 0; mt < 2; mt++)
                #pragma unroll
                for (int n = 0; n < 16; n++)
                    #pragma unroll
                    for (int q = 0; q < 4; q++) acc[mt][n][q] = 0.f;
            #pragma unroll
            for (int k = 0; k < 8; k++) {
                uint32_t a0[4], a1[4];
                ldsm4(a0, aA + k*32);
                ldsm4(a1, aA + 16*STR + k*32);
                #pragma unroll
                for (int n2 = 0; n2 < 8; n2++) {
                    uint32_t b[4];
                    ldsm4(b, bB2 + n2*(16*STR) + k*32);
                    mma16816(acc[0][2*n2],   a0, b[0], b[1]);
                    mma16816(acc[1][2*n2],   a1, b[0], b[1]);
                    mma16816(acc[0][2*n2+1], a0, b[2], b[3]);
                    mma16816(acc[1][2*n2+1], a1, b[2], b[3]);
                }
            }
            #pragma unroll
            for (int mt = 0; mt < 2; mt++) {
                int r0 = m0 + mt*16 + g4;
                #pragma unroll
                for (int n = 0; n < 16; n++) {
                    int col = n*8 + tig*2;
                    *(uint32_t*)(sm + O_AH + (uint32_t)r0*STR + col*2) =
                        packh2(fmaxf(acc[mt][n][0] + b2s[col], 0.f),
                               fmaxf(acc[mt][n][1] + b2s[col+1], 0.f));
                    *(uint32_t*)(sm + O_AH + (uint32_t)(r0+8)*STR + col*2) =
                        packh2(fmaxf(acc[mt][n][2] + b2s[col], 0.f),
                               fmaxf(acc[mt][n][3] + b2s[col+1], 0.f));
                }
            }
        }
        __syncwarp();

        // layer 3: relu(h2 @ W3 + b3), mask, column-max
        {
            int ncnt = meta[wid >> 1];
            int rb0  = (wid & 1) * 32;
            #pragma unroll
            for (int nh = 0; nh < 2; nh++) {
                float acc[2][16][4];
                #pragma unroll
                for (int mt = 0; mt < 2; mt++)
                    #pragma unroll
                    for (int n = 0; n < 16; n++)
                        #pragma unroll
                        for (int q = 0; q < 4; q++) acc[mt][n][q] = 0.f;
                #pragma unroll
                for (int k = 0; k < 8; k++) {
                    uint32_t a0[4], a1[4];
                    ldsm4(a0, aA + k*32);
                    ldsm4(a1, aA + 16*STR + k*32);
                    #pragma unroll
                    for (int n2 = 0; n2 < 8; n2++) {
                        uint32_t b[4];
                        ldsm4(b, bB3 + (nh*128 + n2*16)*STR + k*32);
                        mma16816(acc[0][2*n2],   a0, b[0], b[1]);
                        mma16816(acc[1][2*n2],   a1, b[0], b[1]);
                        mma16816(acc[0][2*n2+1], a0, b[2], b[3]);
                        mma16816(acc[1][2*n2+1], a1, b[2], b[3]);
                    }
                }
                #pragma unroll
                for (int n = 0; n < 16; n++) {
                    int col = nh*128 + n*8 + tig*2;
                    float bv0 = b3s[col], bv1 = b3s[col+1];
                    float mx0 = -1e30f, mx1 = -1e30f;
                    #pragma unroll
                    for (int mt = 0; mt < 2; mt++) {
                        int rlo = rb0 + mt*16 + g4;
                        bool vlo = rlo < ncnt, vhi = (rlo + 8) < ncnt;
                        if (vlo) {
                            mx0 = fmaxf(mx0, fmaxf(acc[mt][n][0] + bv0, 0.f));
                            mx1 = fmaxf(mx1, fmaxf(acc[mt][n][1] + bv1, 0.f));
                        }
                        if (vhi) {
                            mx0 = fmaxf(mx0, fmaxf(acc[mt][n][2] + bv0, 0.f));
                            mx1 = fmaxf(mx1, fmaxf(acc[mt][n][3] + bv1, 0.f));
                        }
                    }
                    #pragma unroll
                    for (int o = 4; o <= 16; o <<= 1) {
                        mx0 = fmaxf(mx0, __shfl_xor_sync(0xffffffffu, mx0, o));
                        mx1 = fmaxf(mx1, __shfl_xor_sync(0xffffffffu, mx1, o));
                    }
                    if (g4 == 0) {
                        part[wid*256 + col]     = mx0;
                        part[wid*256 + col + 1] = mx1;
                    }
                }
            }
        }
        __syncthreads();

        {
            int col = t;
            #pragma unroll
            for (int cl = 0; cl < 4; cl++) {
                float v = fmaxf(part[(2*cl)*256 + (col & 255)], part[(2*cl + 1)*256 + (col & 255)]);
                if (col < 256)
                    out[(size_t)(c0 + cl)*256 + col] = (meta[cl] > 0) ? v : 0.f;
            }
        }
        __syncthreads();
    }
}

// ============================================================
// 4) Tail outputs
// ============================================================
__global__ void tail_kernel(const float* __restrict__ pos, float* __restrict__ out,
                            int write_tail) {
    int i = blockIdx.x * blockDim.x + threadIdx.x;
    if (i >= NCTR || !write_tail) return;
    int fi = g_idx[i];
    out[POS_OFF + 3*i + 0] = pos[3*fi + 0];
    out[POS_OFF + 3*i + 1] = pos[3*fi + 1];
    out[POS_OFF + 3*i + 2] = pos[3*fi + 2];
    out[BATCH_OFF + i] = (float)(fi >> 12);
    out[SEED_OFF  + i] = (float)fi;
}

// ============================================================
extern "C" void kernel_launch(void* const* d_in, const int* in_sizes, int n_in,
                              void* d_out, int out_size) {
    const float* x   = (const float*)d_in[0];
    const float* pos = (const float*)d_in[1];
    const float* W1  = (const float*)d_in[4];
    const float* b1  = (const float*)d_in[5];
    const float* W2  = (const float*)d_in[6];
    const float* b2  = (const float*)d_in[7];
    const float* W3  = (const float*)d_in[8];
    const float* b3  = (const float*)d_in[9];
    float* out = (float*)d_out;

    cudaFuncSetAttribute(fps_kernel, cudaFuncAttributeMaxDynamicSharedMemorySize, FPS_SMEM);
    cudaFuncSetAttribute(edge_kernel, cudaFuncAttributeMaxDynamicSharedMemorySize, SMEM_EDGE);

    fps_kernel<<<NB, 512, FPS_SMEM>>>(pos);
    nbr_kernel<<<NCTR, 256>>>(pos);
    qb_kernel<<<NB*NPTS/QPB, 128>>>(x, pos, W1, b1);
    edge_kernel<<<148, 256, SMEM_EDGE>>>(pos, W1, W2, b2, W3, b3, out);
    tail_kernel<<<(NCTR + 255)/256, 256>>>(pos, out, out_size >= TOTAL_OUT ? 1 : 0);
}